// round 14
// baseline (speedup 1.0000x reference)
#include <cuda_runtime.h>

// Problem shape fixed by setup_inputs(): B=16, C=1024, H=W=32, NH=16.
#define B_  16
#define C_  1024
#define H_  32
#define W_  32
#define HW_ (H_*W_)
#define NH_ 16
#define P_  (H_*W_)       // 1024
#define N_  (P_+1)        // 1025
#define K_  10

#define NB1_ 2064         // bulk kernel blocks (>= 2048 for 8-float4/thread copy)
#define NT1_ 256

// Scratch (__device__ globals; no allocations allowed)
__device__ float        g_cls[B_][P_];        // sum over heads of cls attn
__device__ float        g_diag[B_*NH_][P_];   // per-head diagonal values (no atomics)
__device__ int          g_cpos[B_][K_];       // center positions (top-k)
__device__ int          g_nbr[B_][K_][8];     // clipped neighbor positions
__device__ unsigned int g_win[B_][K_];        // winner bitmask per slot

__constant__ int c_dy[8] = {-1,-1,-1, 0, 0, 1, 1, 1};
__constant__ int c_dx[8] = {-1, 0, 1,-1, 1,-1, 0, 1};

// ---------------------------------------------------------------------------
// Launch 1: bulk. Role-split blocks, NO inter-block dependencies:
//   blocks 0..15     : cls row sums (coalesced)
//   blocks 16..1039  : one diag item each (bh, quarter) -> g_diag plain store
//   ALL blocks       : copy, 8 x float4 per thread STATICALLY BATCHED (MLP=8)
// ---------------------------------------------------------------------------
__global__ void __launch_bounds__(NT1_) bulk_kernel(const float* __restrict__ fm,
                                                    const float* __restrict__ attn,
                                                    float* __restrict__ out) {
    int blk = blockIdx.x;
    int t   = threadIdx.x;

    if (blk < B_) {
        // cls sums for batch blk
        const float* base = attn + (size_t)blk * NH_ * N_ * N_;
#pragma unroll
        for (int u = 0; u < 4; u++) {
            int p = t + u * 256;
            float s = 0.f;
#pragma unroll
            for (int h = 0; h < NH_; h++)
                s += __ldg(base + (size_t)h * N_ * N_ + 1 + p);
            g_cls[blk][p] = s;
        }
    } else if (blk < B_ + B_ * NH_ * 4) {
        // one diag item: 256 scattered diagonal loads, plain store
        int item = blk - B_;
        int bh = item >> 2;
        int p  = (item & 3) * 256 + t;
        g_diag[bh][p] = __ldg(attn + (size_t)bh * N_ * N_ + (size_t)(1 + p) * (N_ + 1));
    }

    // Copy: 8 consecutive float4 per thread, fully unrolled -> 8 loads in flight.
    {
        const float4* s4 = (const float4*)fm;
        float4*       d4 = (float4*)out;
        const long total = (long)(B_ * C_ * HW_) / 4;          // 4,194,304
        long base = ((long)blk * NT1_ + t) * 8;
        if (base + 8 <= total) {
            float4 v[8];
#pragma unroll
            for (int i = 0; i < 8; i++) v[i] = s4[base + i];
#pragma unroll
            for (int i = 0; i < 8; i++) d4[base + i] = v[i];
        } else {
            for (long i = base; i < total; i++) d4[i] = s4[i];
        }
    }
}

// ---------------------------------------------------------------------------
// Launch 2: plan, 1024 threads. Every thread sums its position's 16 heads
// (8x the load parallelism of the 128-thread version) and stores the ranking
// key to smem; 4 warps run the register-resident two-stage top-10; then
// parallel last-writer-wins winner mask. All barriers convergent.
// ratio = cls_sum / (slf_sum + 16e-8)  ==  (cls/16) / (slf/16 + 1e-8)
// ---------------------------------------------------------------------------
__global__ void __launch_bounds__(1024) plan_kernel() {
    int b = blockIdx.x;
    int t = threadIdx.x;
    int w = t >> 5, lane = t & 31;

    __shared__ unsigned long long sh_key[P_];
    __shared__ unsigned long long sh_cand[4 * K_];
    __shared__ int sh_sel[K_];
    __shared__ int sh_tgt[K_ * 8];

    if (t < K_) g_win[b][t] = 0u;

    // Per-position ratio key (1024 threads -> 16 loads each, all independent)
    {
        float slf = 0.f;
#pragma unroll
        for (int h = 0; h < NH_; h++)
            slf += g_diag[b * NH_ + h][t];
        float rt = g_cls[b][t] / (slf + 1.6e-7f);
        // ratio >= 0 -> float bits monotonic as unsigned; tie -> smaller p
        sh_key[t] = ((unsigned long long)__float_as_uint(rt) << 32)
                  | (unsigned)(0xFFFFFFFFu - (unsigned)t);
    }
    __syncthreads();

    // Stage 1: warps 0..3, 8 keys/lane from smem (registers only, no spill)
    if (w < 4) {
        unsigned long long key[8];
#pragma unroll
        for (int u = 0; u < 8; u++)
            key[u] = sh_key[w * 256 + u * 32 + lane];
#pragma unroll
        for (int k = 0; k < K_; k++) {
            unsigned long long lm = 0ull;
#pragma unroll
            for (int u = 0; u < 8; u++)
                if (key[u] > lm) lm = key[u];
            unsigned long long wm = lm;
#pragma unroll
            for (int off = 16; off; off >>= 1) {
                unsigned long long o = __shfl_xor_sync(0xffffffffu, wm, off);
                if (o > wm) wm = o;
            }
#pragma unroll
            for (int u = 0; u < 8; u++)        // static-index removal (keys unique)
                if (key[u] == wm) key[u] = 0ull;
            if (lane == 0) sh_cand[w * K_ + k] = wm;
        }
    }
    __syncthreads();

    // Stage 2: warp 0 selects global top-10 from 40 candidates
    if (w == 0) {
        unsigned long long k0 = (lane < 4 * K_) ? sh_cand[lane] : 0ull;
        unsigned long long k1 = (lane + 32 < 4 * K_) ? sh_cand[lane + 32] : 0ull;
#pragma unroll
        for (int k = 0; k < K_; k++) {
            unsigned long long lm = k0 > k1 ? k0 : k1;
            unsigned long long wm = lm;
#pragma unroll
            for (int off = 16; off; off >>= 1) {
                unsigned long long o = __shfl_xor_sync(0xffffffffu, wm, off);
                if (o > wm) wm = o;
            }
            if (k0 == wm) k0 = 0ull;
            if (k1 == wm) k1 = 0ull;
            if (lane == 0)
                sh_sel[k] = (int)(0xFFFFFFFFu - (unsigned)(wm & 0xFFFFFFFFull));
        }
    }
    __syncthreads();

    // Targets + winner mask (parallel, convergent barriers)
    int q = -1;
    if (t < K_ * 8) {
        int i = t >> 3, j = t & 7;
        int sel = sh_sel[i];
        int r = sel >> 5, c = sel & 31;
        int y = r + c_dy[j]; y = y < 0 ? 0 : (y > H_ - 1 ? H_ - 1 : y);
        int x = c + c_dx[j]; x = x < 0 ? 0 : (x > W_ - 1 ? W_ - 1 : x);
        q = y * W_ + x;
        sh_tgt[t] = q;
        g_nbr[b][i][j] = q;
    }
    if (t < K_) g_cpos[b][t] = sh_sel[t];
    __syncthreads();

    if (t < K_ * 8) {
        int i = t >> 3, j = t & 7;
        // winner iff target is not any center AND no later slot claims it
        bool center = false;
#pragma unroll
        for (int m = 0; m < K_; m++)
            if (q == sh_sel[m]) center = true;
        bool later = false;
        for (int k2 = t + 1; k2 < K_ * 8; k2++)
            if (sh_tgt[k2] == q) later = true;
        if (!center && !later)
            atomicOr(&g_win[b][i], 1u << j);
    }
}

// ---------------------------------------------------------------------------
// Launch 3: fused stats + special-position writes (suppress).
// One block per (b,slot): 512 threads x 2 channels. Winner sets globally
// disjoint (last-writer-wins precomputed) => race-free.
// ---------------------------------------------------------------------------
__global__ void __launch_bounds__(512) suppress_kernel(const float* __restrict__ fm,
                                                       float* __restrict__ out) {
    int blk = blockIdx.x;
    int b = blk / K_, i = blk % K_;
    int cpos = g_cpos[b][i];
    unsigned win = g_win[b][i];
    int np[8];
#pragma unroll
    for (int j = 0; j < 8; j++) np[j] = g_nbr[b][i][j];

    const float* f = fm  + (size_t)b * C_ * HW_;
    float*       o = out + (size_t)b * C_ * HW_;
    int t = threadIdx.x;

    float ov[2];
    float nb[8][2];
    float dot[8] = {0,0,0,0,0,0,0,0};
    float n2[8]  = {0,0,0,0,0,0,0,0};
    float o2 = 0.f;

#pragma unroll
    for (int u = 0; u < 2; u++) {
        int ch = t + u * 512;
        const float* fc = f + (size_t)ch * HW_;
        float v = fc[cpos];
        ov[u] = v;
        o2 += v * v;
#pragma unroll
        for (int j = 0; j < 8; j++) {
            float nv = fc[np[j]];
            nb[j][u] = nv;
            dot[j] += nv * v;
            n2[j]  += nv * nv;
        }
    }

    __shared__ float part[17][16];
    float vals[17];
    vals[0] = o2;
#pragma unroll
    for (int j = 0; j < 8; j++) { vals[1 + j] = dot[j]; vals[9 + j] = n2[j]; }
#pragma unroll
    for (int k = 0; k < 17; k++) {
        float v = vals[k];
#pragma unroll
        for (int off = 16; off; off >>= 1) v += __shfl_down_sync(0xffffffffu, v, off);
        if ((t & 31) == 0) part[k][t >> 5] = v;
    }
    __syncthreads();

    __shared__ float s_w[8], s_str[8];
    if (t < 32) {
        float sums[17];
#pragma unroll
        for (int k = 0; k < 17; k++) {
            float v = (t < 16) ? part[k][t] : 0.f;
#pragma unroll
            for (int off = 8; off; off >>= 1) v += __shfl_down_sync(0xffffffffu, v, off);
            sums[k] = v;   // valid on lane 0
        }
        if (t == 0) {
            float on = fmaxf(sqrtf(sums[0]), 1e-12f);
            float sim[8], z[8];
            float zmax = -1e30f;
#pragma unroll
            for (int j = 0; j < 8; j++) {
                float nn = fmaxf(sqrtf(sums[9 + j]), 1e-12f);
                sim[j] = sums[1 + j] / (nn * on);
                z[j] = fmaxf(1.f - sim[j], 0.f);
                zmax = fmaxf(zmax, z[j]);
            }
            float es = 0.f, e[8];
#pragma unroll
            for (int j = 0; j < 8; j++) { e[j] = expf(z[j] - zmax); es += e[j]; }
            float inv = 1.f / es;
#pragma unroll
            for (int j = 0; j < 8; j++) {
                s_w[j]   = e[j] * inv;
                s_str[j] = fminf(fmaxf(sim[j] * 0.1f, 0.f), 1.f);
            }
        }
    }
    __syncthreads();

    float w[8], str[8];
#pragma unroll
    for (int j = 0; j < 8; j++) { w[j] = s_w[j]; str[j] = s_str[j]; }

#pragma unroll
    for (int u = 0; u < 2; u++) {
        int ch = t + u * 512;
        float* oc = o + (size_t)ch * HW_;
        float wa = 0.f;
#pragma unroll
        for (int j = 0; j < 8; j++) wa += nb[j][u] * w[j];
        oc[cpos] = wa;                                    // center <- wavg
#pragma unroll
        for (int j = 0; j < 8; j++) {
            if ((win >> j) & 1u)
                oc[np[j]] = nb[j][u] - ov[u] * str[j];    // winner
        }
    }
}

// ---------------------------------------------------------------------------
extern "C" void kernel_launch(void* const* d_in, const int* in_sizes, int n_in,
                              void* d_out, int out_size) {
    const float* fm   = (const float*)d_in[0];
    const float* attn = (const float*)d_in[1];
    float* out = (float*)d_out;

    bulk_kernel<<<NB1_, NT1_>>>(fm, attn, out);
    plan_kernel<<<B_, 1024>>>();
    suppress_kernel<<<B_ * K_, 512>>>(fm, out);
}

// round 15
// speedup vs baseline: 1.2263x; 1.2263x over previous
#include <cuda_runtime.h>

// Problem shape fixed by setup_inputs(): B=16, C=1024, H=W=32, NH=16.
#define B_  16
#define C_  1024
#define H_  32
#define W_  32
#define HW_ (H_*W_)
#define NH_ 16
#define P_  (H_*W_)       // 1024
#define N_  (P_+1)        // 1025
#define K_  10

#define NB1_ 2048         // bulk kernel blocks
#define NT1_ 256
#define GRID1_ (NB1_ * NT1_)   // 524288 threads; x8 float4 = 4,194,304 exact

// Scratch (__device__ globals; no allocations allowed)
__device__ float        g_cls[B_][P_];        // sum over heads of cls attn
__device__ float        g_diag[B_*NH_][P_];   // per-head diagonal values (no atomics)
__device__ int          g_cpos[B_][K_];       // center positions (top-k)
__device__ int          g_nbr[B_][K_][8];     // clipped neighbor positions
__device__ unsigned int g_win[B_][K_];        // winner bitmask per slot

__constant__ int c_dy[8] = {-1,-1,-1, 0, 0, 1, 1, 1};
__constant__ int c_dx[8] = {-1, 0, 1,-1, 1,-1, 0, 1};

// ---------------------------------------------------------------------------
// Launch 1: bulk. Role-split blocks, NO inter-block dependencies:
//   blocks 0..15     : cls row sums (coalesced)
//   blocks 16..1039  : one diag item each (bh, quarter) -> g_diag plain store
//   ALL blocks       : copy, 8 x float4 per thread, COALESCED + BATCHED:
//                      thread handles {i + k*GRID}: lanes adjacent within each
//                      LDG (full 128B lines) AND 8 independent loads in flight.
// ---------------------------------------------------------------------------
__global__ void __launch_bounds__(NT1_) bulk_kernel(const float* __restrict__ fm,
                                                    const float* __restrict__ attn,
                                                    float* __restrict__ out) {
    int blk = blockIdx.x;
    int t   = threadIdx.x;

    if (blk < B_) {
        // cls sums for batch blk
        const float* base = attn + (size_t)blk * NH_ * N_ * N_;
#pragma unroll
        for (int u = 0; u < 4; u++) {
            int p = t + u * 256;
            float s = 0.f;
#pragma unroll
            for (int h = 0; h < NH_; h++)
                s += __ldg(base + (size_t)h * N_ * N_ + 1 + p);
            g_cls[blk][p] = s;
        }
    } else if (blk < B_ + B_ * NH_ * 4) {
        // one diag item: 256 scattered diagonal loads, plain store
        int item = blk - B_;
        int bh = item >> 2;
        int p  = (item & 3) * 256 + t;
        g_diag[bh][p] = __ldg(attn + (size_t)bh * N_ * N_ + (size_t)(1 + p) * (N_ + 1));
    }

    // Copy: coalesced grid-layout, statically unrolled 8-deep.
    {
        const float4* s4 = (const float4*)fm;
        float4*       d4 = (float4*)out;
        int idx = blk * NT1_ + t;
        float4 v[8];
#pragma unroll
        for (int i = 0; i < 8; i++) v[i] = s4[idx + i * GRID1_];
#pragma unroll
        for (int i = 0; i < 8; i++) d4[idx + i * GRID1_] = v[i];
    }
}

// ---------------------------------------------------------------------------
// Launch 2: plan, 1024 threads. Every thread sums its position's 16 heads
// and stores the ranking key to smem; 4 warps run the register-resident
// two-stage top-10; then parallel last-writer-wins winner mask.
// ratio = cls_sum / (slf_sum + 16e-8)  ==  (cls/16) / (slf/16 + 1e-8)
// ---------------------------------------------------------------------------
__global__ void __launch_bounds__(1024) plan_kernel() {
    int b = blockIdx.x;
    int t = threadIdx.x;
    int w = t >> 5, lane = t & 31;

    __shared__ unsigned long long sh_key[P_];
    __shared__ unsigned long long sh_cand[4 * K_];
    __shared__ int sh_sel[K_];
    __shared__ int sh_tgt[K_ * 8];

    if (t < K_) g_win[b][t] = 0u;

    // Per-position ratio key (1024 threads -> 16 loads each, all independent)
    {
        float slf = 0.f;
#pragma unroll
        for (int h = 0; h < NH_; h++)
            slf += g_diag[b * NH_ + h][t];
        float rt = g_cls[b][t] / (slf + 1.6e-7f);
        // ratio >= 0 -> float bits monotonic as unsigned; tie -> smaller p
        sh_key[t] = ((unsigned long long)__float_as_uint(rt) << 32)
                  | (unsigned)(0xFFFFFFFFu - (unsigned)t);
    }
    __syncthreads();

    // Stage 1: warps 0..3, 8 keys/lane from smem (registers only, no spill)
    if (w < 4) {
        unsigned long long key[8];
#pragma unroll
        for (int u = 0; u < 8; u++)
            key[u] = sh_key[w * 256 + u * 32 + lane];
#pragma unroll
        for (int k = 0; k < K_; k++) {
            unsigned long long lm = 0ull;
#pragma unroll
            for (int u = 0; u < 8; u++)
                if (key[u] > lm) lm = key[u];
            unsigned long long wm = lm;
#pragma unroll
            for (int off = 16; off; off >>= 1) {
                unsigned long long o = __shfl_xor_sync(0xffffffffu, wm, off);
                if (o > wm) wm = o;
            }
#pragma unroll
            for (int u = 0; u < 8; u++)        // static-index removal (keys unique)
                if (key[u] == wm) key[u] = 0ull;
            if (lane == 0) sh_cand[w * K_ + k] = wm;
        }
    }
    __syncthreads();

    // Stage 2: warp 0 selects global top-10 from 40 candidates
    if (w == 0) {
        unsigned long long k0 = (lane < 4 * K_) ? sh_cand[lane] : 0ull;
        unsigned long long k1 = (lane + 32 < 4 * K_) ? sh_cand[lane + 32] : 0ull;
#pragma unroll
        for (int k = 0; k < K_; k++) {
            unsigned long long lm = k0 > k1 ? k0 : k1;
            unsigned long long wm = lm;
#pragma unroll
            for (int off = 16; off; off >>= 1) {
                unsigned long long o = __shfl_xor_sync(0xffffffffu, wm, off);
                if (o > wm) wm = o;
            }
            if (k0 == wm) k0 = 0ull;
            if (k1 == wm) k1 = 0ull;
            if (lane == 0)
                sh_sel[k] = (int)(0xFFFFFFFFu - (unsigned)(wm & 0xFFFFFFFFull));
        }
    }
    __syncthreads();

    // Targets + winner mask (parallel, convergent barriers)
    int q = -1;
    if (t < K_ * 8) {
        int i = t >> 3, j = t & 7;
        int sel = sh_sel[i];
        int r = sel >> 5, c = sel & 31;
        int y = r + c_dy[j]; y = y < 0 ? 0 : (y > H_ - 1 ? H_ - 1 : y);
        int x = c + c_dx[j]; x = x < 0 ? 0 : (x > W_ - 1 ? W_ - 1 : x);
        q = y * W_ + x;
        sh_tgt[t] = q;
        g_nbr[b][i][j] = q;
    }
    if (t < K_) g_cpos[b][t] = sh_sel[t];
    __syncthreads();

    if (t < K_ * 8) {
        int i = t >> 3, j = t & 7;
        // winner iff target is not any center AND no later slot claims it
        bool center = false;
#pragma unroll
        for (int m = 0; m < K_; m++)
            if (q == sh_sel[m]) center = true;
        bool later = false;
        for (int k2 = t + 1; k2 < K_ * 8; k2++)
            if (sh_tgt[k2] == q) later = true;
        if (!center && !later)
            atomicOr(&g_win[b][i], 1u << j);
    }
}

// ---------------------------------------------------------------------------
// Launch 3: fused stats + special-position writes (suppress).
// One block per (b,slot): 512 threads x 2 channels. Winner sets globally
// disjoint (last-writer-wins precomputed) => race-free.
// ---------------------------------------------------------------------------
__global__ void __launch_bounds__(512) suppress_kernel(const float* __restrict__ fm,
                                                       float* __restrict__ out) {
    int blk = blockIdx.x;
    int b = blk / K_, i = blk % K_;
    int cpos = g_cpos[b][i];
    unsigned win = g_win[b][i];
    int np[8];
#pragma unroll
    for (int j = 0; j < 8; j++) np[j] = g_nbr[b][i][j];

    const float* f = fm  + (size_t)b * C_ * HW_;
    float*       o = out + (size_t)b * C_ * HW_;
    int t = threadIdx.x;

    float ov[2];
    float nb[8][2];
    float dot[8] = {0,0,0,0,0,0,0,0};
    float n2[8]  = {0,0,0,0,0,0,0,0};
    float o2 = 0.f;

#pragma unroll
    for (int u = 0; u < 2; u++) {
        int ch = t + u * 512;
        const float* fc = f + (size_t)ch * HW_;
        float v = fc[cpos];
        ov[u] = v;
        o2 += v * v;
#pragma unroll
        for (int j = 0; j < 8; j++) {
            float nv = fc[np[j]];
            nb[j][u] = nv;
            dot[j] += nv * v;
            n2[j]  += nv * nv;
        }
    }

    __shared__ float part[17][16];
    float vals[17];
    vals[0] = o2;
#pragma unroll
    for (int j = 0; j < 8; j++) { vals[1 + j] = dot[j]; vals[9 + j] = n2[j]; }
#pragma unroll
    for (int k = 0; k < 17; k++) {
        float v = vals[k];
#pragma unroll
        for (int off = 16; off; off >>= 1) v += __shfl_down_sync(0xffffffffu, v, off);
        if ((t & 31) == 0) part[k][t >> 5] = v;
    }
    __syncthreads();

    __shared__ float s_w[8], s_str[8];
    if (t < 32) {
        float sums[17];
#pragma unroll
        for (int k = 0; k < 17; k++) {
            float v = (t < 16) ? part[k][t] : 0.f;
#pragma unroll
            for (int off = 8; off; off >>= 1) v += __shfl_down_sync(0xffffffffu, v, off);
            sums[k] = v;   // valid on lane 0
        }
        if (t == 0) {
            float on = fmaxf(sqrtf(sums[0]), 1e-12f);
            float sim[8], z[8];
            float zmax = -1e30f;
#pragma unroll
            for (int j = 0; j < 8; j++) {
                float nn = fmaxf(sqrtf(sums[9 + j]), 1e-12f);
                sim[j] = sums[1 + j] / (nn * on);
                z[j] = fmaxf(1.f - sim[j], 0.f);
                zmax = fmaxf(zmax, z[j]);
            }
            float es = 0.f, e[8];
#pragma unroll
            for (int j = 0; j < 8; j++) { e[j] = expf(z[j] - zmax); es += e[j]; }
            float inv = 1.f / es;
#pragma unroll
            for (int j = 0; j < 8; j++) {
                s_w[j]   = e[j] * inv;
                s_str[j] = fminf(fmaxf(sim[j] * 0.1f, 0.f), 1.f);
            }
        }
    }
    __syncthreads();

    float w[8], str[8];
#pragma unroll
    for (int j = 0; j < 8; j++) { w[j] = s_w[j]; str[j] = s_str[j]; }

#pragma unroll
    for (int u = 0; u < 2; u++) {
        int ch = t + u * 512;
        float* oc = o + (size_t)ch * HW_;
        float wa = 0.f;
#pragma unroll
        for (int j = 0; j < 8; j++) wa += nb[j][u] * w[j];
        oc[cpos] = wa;                                    // center <- wavg
#pragma unroll
        for (int j = 0; j < 8; j++) {
            if ((win >> j) & 1u)
                oc[np[j]] = nb[j][u] - ov[u] * str[j];    // winner
        }
    }
}

// ---------------------------------------------------------------------------
extern "C" void kernel_launch(void* const* d_in, const int* in_sizes, int n_in,
                              void* d_out, int out_size) {
    const float* fm   = (const float*)d_in[0];
    const float* attn = (const float*)d_in[1];
    float* out = (float*)d_out;

    bulk_kernel<<<NB1_, NT1_>>>(fm, attn, out);
    plan_kernel<<<B_, 1024>>>();
    suppress_kernel<<<B_ * K_, 512>>>(fm, out);
}

// round 16
// speedup vs baseline: 1.2742x; 1.0390x over previous
#include <cuda_runtime.h>

// Problem shape fixed by setup_inputs(): B=16, C=1024, H=W=32, NH=16.
#define B_  16
#define C_  1024
#define H_  32
#define W_  32
#define HW_ (H_*W_)
#define NH_ 16
#define P_  (H_*W_)       // 1024
#define N_  (P_+1)        // 1025
#define K_  10

#define NB1_ 2048         // bulk kernel blocks
#define NT1_ 256
#define GRID1_ (NB1_ * NT1_)   // 524288 threads; x8 float4 = 4,194,304 exact

// Scratch (__device__ globals; no allocations allowed)
__device__ float g_cls[B_][P_];        // sum over heads of cls attn
__device__ float g_diag[B_*NH_][P_];   // per-head diagonal values (no atomics)

__constant__ int c_dy[8] = {-1,-1,-1, 0, 0, 1, 1, 1};
__constant__ int c_dx[8] = {-1, 0, 1,-1, 1,-1, 0, 1};

// ---------------------------------------------------------------------------
// Launch 1: bulk. Role-split blocks, NO inter-block dependencies:
//   blocks 0..15     : cls row sums (coalesced)
//   blocks 16..1039  : one diag item each (bh, quarter) -> g_diag plain store
//   ALL blocks       : copy, 8 x float4 per thread, coalesced grid layout.
// Copy uses streaming ld/st (evict-first) to keep L2 for the attn working set.
// ---------------------------------------------------------------------------
__global__ void __launch_bounds__(NT1_) bulk_kernel(const float* __restrict__ fm,
                                                    const float* __restrict__ attn,
                                                    float* __restrict__ out) {
    int blk = blockIdx.x;
    int t   = threadIdx.x;

    if (blk < B_) {
        // cls sums for batch blk
        const float* base = attn + (size_t)blk * NH_ * N_ * N_;
#pragma unroll
        for (int u = 0; u < 4; u++) {
            int p = t + u * 256;
            float s = 0.f;
#pragma unroll
            for (int h = 0; h < NH_; h++)
                s += __ldg(base + (size_t)h * N_ * N_ + 1 + p);
            g_cls[blk][p] = s;
        }
    } else if (blk < B_ + B_ * NH_ * 4) {
        // one diag item: 256 scattered diagonal loads, plain store
        int item = blk - B_;
        int bh = item >> 2;
        int p  = (item & 3) * 256 + t;
        g_diag[bh][p] = __ldg(attn + (size_t)bh * N_ * N_ + (size_t)(1 + p) * (N_ + 1));
    }

    // Copy: coalesced grid-layout, statically unrolled 8-deep, streaming.
    {
        const float4* s4 = (const float4*)fm;
        float4*       d4 = (float4*)out;
        int idx = blk * NT1_ + t;
        float4 v[8];
#pragma unroll
        for (int i = 0; i < 8; i++) v[i] = __ldcs(s4 + idx + i * GRID1_);
#pragma unroll
        for (int i = 0; i < 8; i++) __stcs(d4 + idx + i * GRID1_, v[i]);
    }
}

// ---------------------------------------------------------------------------
// Launch 2: SELF-PLANNING suppress. One block per (b,slot), 512 threads.
// Each block redundantly recomputes its batch's plan from g_cls/g_diag
// (L2-resident, ~2-3us) entirely in shared memory: two-stage top-10 (no
// register spills), slot targets, and THIS slot's last-writer-wins winner
// bits (block-local, one shared atomicOr). Then the fused stats + write
// phase as before. Winner sets across blocks remain globally disjoint.
// ---------------------------------------------------------------------------
__global__ void __launch_bounds__(512) suppress_kernel(const float* __restrict__ fm,
                                                       float* __restrict__ out) {
    int blk = blockIdx.x;
    int b = blk / K_, i = blk % K_;
    int t = threadIdx.x;
    int w = t >> 5, lane = t & 31;

    __shared__ unsigned long long sh_key[P_];
    __shared__ unsigned long long sh_cand[4 * K_];
    __shared__ int sh_sel[K_];
    __shared__ int sh_tgt[K_ * 8];
    __shared__ unsigned s_win;
    __shared__ float part[17][16];
    __shared__ float s_w[8], s_str[8];

    if (t == 0) s_win = 0u;

    // ---- Plan phase: ratio keys (512 threads x 2 positions, coalesced) ----
#pragma unroll
    for (int u = 0; u < 2; u++) {
        int p = t + u * 512;
        float slf = 0.f;
#pragma unroll
        for (int h = 0; h < NH_; h++)
            slf += g_diag[b * NH_ + h][p];
        float rt = g_cls[b][p] / (slf + 1.6e-7f);
        // ratio = cls_sum/(slf_sum+16e-8) == (cls/16)/(slf/16+1e-8); >= 0 so
        // float bits are monotonic as unsigned; tie -> smaller p
        sh_key[p] = ((unsigned long long)__float_as_uint(rt) << 32)
                  | (unsigned)(0xFFFFFFFFu - (unsigned)p);
    }
    __syncthreads();

    // Stage 1: warps 0..3, 8 keys/lane from smem (registers only, no spill)
    if (w < 4) {
        unsigned long long key[8];
#pragma unroll
        for (int u = 0; u < 8; u++)
            key[u] = sh_key[w * 256 + u * 32 + lane];
#pragma unroll
        for (int k = 0; k < K_; k++) {
            unsigned long long lm = 0ull;
#pragma unroll
            for (int u = 0; u < 8; u++)
                if (key[u] > lm) lm = key[u];
            unsigned long long wm = lm;
#pragma unroll
            for (int off = 16; off; off >>= 1) {
                unsigned long long o = __shfl_xor_sync(0xffffffffu, wm, off);
                if (o > wm) wm = o;
            }
#pragma unroll
            for (int u = 0; u < 8; u++)        // static-index removal (keys unique)
                if (key[u] == wm) key[u] = 0ull;
            if (lane == 0) sh_cand[w * K_ + k] = wm;
        }
    }
    __syncthreads();

    // Stage 2: warp 0 selects global top-10 from 40 candidates
    if (w == 0) {
        unsigned long long k0 = (lane < 4 * K_) ? sh_cand[lane] : 0ull;
        unsigned long long k1 = (lane + 32 < 4 * K_) ? sh_cand[lane + 32] : 0ull;
#pragma unroll
        for (int k = 0; k < K_; k++) {
            unsigned long long lm = k0 > k1 ? k0 : k1;
            unsigned long long wm = lm;
#pragma unroll
            for (int off = 16; off; off >>= 1) {
                unsigned long long o = __shfl_xor_sync(0xffffffffu, wm, off);
                if (o > wm) wm = o;
            }
            if (k0 == wm) k0 = 0ull;
            if (k1 == wm) k1 = 0ull;
            if (lane == 0)
                sh_sel[k] = (int)(0xFFFFFFFFu - (unsigned)(wm & 0xFFFFFFFFull));
        }
    }
    __syncthreads();

    // Targets for all 80 slots
    if (t < K_ * 8) {
        int si = t >> 3, j = t & 7;
        int sel = sh_sel[si];
        int r = sel >> 5, c = sel & 31;
        int y = r + c_dy[j]; y = y < 0 ? 0 : (y > H_ - 1 ? H_ - 1 : y);
        int x = c + c_dx[j]; x = x < 0 ? 0 : (x > W_ - 1 ? W_ - 1 : x);
        sh_tgt[t] = y * W_ + x;
    }
    __syncthreads();

    // Winner bits for THIS block's slot i only (threads 0..7, shared OR)
    if (t < 8) {
        int j = t;
        int q = sh_tgt[i * 8 + j];
        bool center = false;
#pragma unroll
        for (int m = 0; m < K_; m++)
            if (q == sh_sel[m]) center = true;
        bool later = false;
        for (int k2 = i * 8 + j + 1; k2 < K_ * 8; k2++)
            if (sh_tgt[k2] == q) later = true;
        if (!center && !later)
            atomicOr(&s_win, 1u << j);
    }
    __syncthreads();

    // ---- Suppress phase (identical math to R15's passing version) ----
    int cpos = sh_sel[i];
    unsigned win = s_win;
    int np[8];
#pragma unroll
    for (int j = 0; j < 8; j++) np[j] = sh_tgt[i * 8 + j];

    const float* f = fm  + (size_t)b * C_ * HW_;
    float*       o = out + (size_t)b * C_ * HW_;

    float ov[2];
    float nb[8][2];
    float dot[8] = {0,0,0,0,0,0,0,0};
    float n2[8]  = {0,0,0,0,0,0,0,0};
    float o2 = 0.f;

#pragma unroll
    for (int u = 0; u < 2; u++) {
        int ch = t + u * 512;
        const float* fc = f + (size_t)ch * HW_;
        float v = fc[cpos];
        ov[u] = v;
        o2 += v * v;
#pragma unroll
        for (int j = 0; j < 8; j++) {
            float nv = fc[np[j]];
            nb[j][u] = nv;
            dot[j] += nv * v;
            n2[j]  += nv * nv;
        }
    }

    float vals[17];
    vals[0] = o2;
#pragma unroll
    for (int j = 0; j < 8; j++) { vals[1 + j] = dot[j]; vals[9 + j] = n2[j]; }
#pragma unroll
    for (int k = 0; k < 17; k++) {
        float v = vals[k];
#pragma unroll
        for (int off = 16; off; off >>= 1) v += __shfl_down_sync(0xffffffffu, v, off);
        if ((t & 31) == 0) part[k][t >> 5] = v;
    }
    __syncthreads();

    if (t < 32) {
        float sums[17];
#pragma unroll
        for (int k = 0; k < 17; k++) {
            float v = (t < 16) ? part[k][t] : 0.f;
#pragma unroll
            for (int off = 8; off; off >>= 1) v += __shfl_down_sync(0xffffffffu, v, off);
            sums[k] = v;   // valid on lane 0
        }
        if (t == 0) {
            float on = fmaxf(sqrtf(sums[0]), 1e-12f);
            float sim[8], z[8];
            float zmax = -1e30f;
#pragma unroll
            for (int j = 0; j < 8; j++) {
                float nn = fmaxf(sqrtf(sums[9 + j]), 1e-12f);
                sim[j] = sums[1 + j] / (nn * on);
                z[j] = fmaxf(1.f - sim[j], 0.f);
                zmax = fmaxf(zmax, z[j]);
            }
            float es = 0.f, e[8];
#pragma unroll
            for (int j = 0; j < 8; j++) { e[j] = expf(z[j] - zmax); es += e[j]; }
            float inv = 1.f / es;
#pragma unroll
            for (int j = 0; j < 8; j++) {
                s_w[j]   = e[j] * inv;
                s_str[j] = fminf(fmaxf(sim[j] * 0.1f, 0.f), 1.f);
            }
        }
    }
    __syncthreads();

    float wgt[8], str[8];
#pragma unroll
    for (int j = 0; j < 8; j++) { wgt[j] = s_w[j]; str[j] = s_str[j]; }

#pragma unroll
    for (int u = 0; u < 2; u++) {
        int ch = t + u * 512;
        float* oc = o + (size_t)ch * HW_;
        float wa = 0.f;
#pragma unroll
        for (int j = 0; j < 8; j++) wa += nb[j][u] * wgt[j];
        oc[cpos] = wa;                                    // center <- wavg
#pragma unroll
        for (int j = 0; j < 8; j++) {
            if ((win >> j) & 1u)
                oc[np[j]] = nb[j][u] - ov[u] * str[j];    // winner
        }
    }
}

// ---------------------------------------------------------------------------
extern "C" void kernel_launch(void* const* d_in, const int* in_sizes, int n_in,
                              void* d_out, int out_size) {
    const float* fm   = (const float*)d_in[0];
    const float* attn = (const float*)d_in[1];
    float* out = (float*)d_out;

    bulk_kernel<<<NB1_, NT1_>>>(fm, attn, out);
    suppress_kernel<<<B_ * K_, 512>>>(fm, out);
}